// round 15
// baseline (speedup 1.0000x reference)
#include <cuda_runtime.h>
#include <cuda_fp16.h>
#include <cstdint>
#include <math.h>

#define BB    8192
#define D_IN  512
#define H1    4096
#define CH    256
#define HR    1024
#define H2    4096
#define D_OUTN 512

// ---------------- scratch (device globals; no allocation allowed) ----------
__device__ __half g_xh [(size_t)BB * D_IN];
__device__ __half g_wh [(size_t)7602176];       // all weights, fp16
__device__ __half g_ah [(size_t)BB * H1];
__device__ __half g_xrh[(size_t)BB * CH];
__device__ __half g_g1h[(size_t)BB * HR];
__device__ __half g_g2h[(size_t)BB * HR];
__device__ __half g_x2h[(size_t)BB * CH];
__device__ __half g_th [(size_t)BB * H2];
__device__ float  g_p2 [(size_t)2 * BB * CH];   // split-K partials for G2

#define OFF_W1  0
#define OFF_W2  2097152
#define OFF_WR1 3145728
#define OFF_WR2 3407872
#define OFF_W3  4456448
#define OFF_W4  5505024

// ---------------- helpers ----------------------------------------------------
__device__ __forceinline__ uint32_t smem_u32(const void* p) {
    uint32_t a;
    asm("{ .reg .u64 t; cvta.to.shared.u64 t, %1; cvt.u32.u64 %0, t; }"
        : "=r"(a) : "l"(p));
    return a;
}

__device__ __forceinline__ void cp_async16(uint32_t dst, const void* src) {
    asm volatile("cp.async.cg.shared.global [%0], [%1], 16;"
        :: "r"(dst), "l"(src) : "memory");
}
__device__ __forceinline__ void cp_commit() {
    asm volatile("cp.async.commit_group;" ::: "memory");
}
template <int N>
__device__ __forceinline__ void cp_wait() {
    asm volatile("cp.async.wait_group %0;" :: "n"(N) : "memory");
}

__device__ __forceinline__ void ldsm4(uint32_t& r0, uint32_t& r1,
                                      uint32_t& r2, uint32_t& r3, uint32_t a) {
    asm volatile("ldmatrix.sync.aligned.m8n8.x4.shared.b16 {%0,%1,%2,%3}, [%4];"
        : "=r"(r0), "=r"(r1), "=r"(r2), "=r"(r3) : "r"(a));
}

__device__ __forceinline__ void mma_f16(float* d, const uint32_t* a,
                                        uint32_t b0, uint32_t b1) {
    asm volatile(
        "mma.sync.aligned.m16n8k16.row.col.f32.f16.f16.f32 "
        "{%0,%1,%2,%3}, {%4,%5,%6,%7}, {%8,%9}, {%0,%1,%2,%3};"
        : "+f"(d[0]), "+f"(d[1]), "+f"(d[2]), "+f"(d[3])
        : "r"(a[0]), "r"(a[1]), "r"(a[2]), "r"(a[3]), "r"(b0), "r"(b1));
}

// ---------------- single fused fp32 -> fp16 conversion pass ------------------
struct ConvArgs {
    const float* src[8];
    __half*      dst[8];
    int          n4[8];
};

__global__ void conv_all_kernel(ConvArgs a) {
    const int stride = gridDim.x * blockDim.x;
    const int t0 = blockIdx.x * blockDim.x + threadIdx.x;
#pragma unroll
    for (int s = 0; s < 8; ++s) {
        const float4* sp = (const float4*)a.src[s];
        __half2* dp = (__half2*)a.dst[s];
        const int n = a.n4[s];
        for (int i = t0; i < n; i += stride) {
            float4 v = sp[i];
            dp[2 * i]     = __floats2half2_rn(v.x, v.y);
            dp[2 * i + 1] = __floats2half2_rn(v.z, v.w);
        }
    }
}

// =============== fp16 GEMM: 128x128x64, 3-stage, 2 CTAs/SM (R7 best) =========
#define BM 128
#define BN 128
#define BK 64
#define ROWB 144                      // padded row bytes (72 halfs)
#define ATILE_B (128 * ROWB)          // 18432
#define STAGE_B (2 * ATILE_B)         // 36864 (A + B)
#define SMEM3   (3 * STAGE_B)         // 110592

template <int ACT, typename OutT>     // ACT: 0 none, 1 relu, 2 tanh
__global__ void __launch_bounds__(256, 2)
gemm_h(const __half* __restrict__ A, const __half* __restrict__ W,
       const float* __restrict__ bias, OutT* __restrict__ C,
       int M, int N, int K)
{
    extern __shared__ char smc[];
    const uint32_t sb = smem_u32(smc);
    const int tid  = threadIdx.x;
    const int wid  = tid >> 5, lane = tid & 31;
    const int g    = lane >> 2, c = lane & 3;
    const int wm   = wid & 3, wn = wid >> 2;      // warp grid 4(M) x 2(N)
    const int bm   = blockIdx.x * BM;
    const int bn   = blockIdx.y * BN;

    const int lrow = tid >> 1;
    const int lsel = tid & 1;
    const __half* Ag = A + (size_t)(bm + lrow) * K + lsel * 32;
    const __half* Bg = W + (size_t)(bn + lrow) * K + lsel * 32;
    const uint32_t stA = sb + (uint32_t)(lrow * ROWB + lsel * 64);
    const uint32_t stB = stA + ATILE_B;

    float acc[2][8][4];
#pragma unroll
    for (int mt = 0; mt < 2; mt++)
#pragma unroll
        for (int nt = 0; nt < 8; nt++)
#pragma unroll
            for (int r = 0; r < 4; r++) acc[mt][nt][r] = 0.0f;

    const int nk = K / BK;

#pragma unroll
    for (int s = 0; s < 2; ++s) {
        const uint32_t base = s * STAGE_B;
        const int off = s * BK;
#pragma unroll
        for (int i = 0; i < 4; i++) {
            cp_async16(stA + base + i * 16, Ag + off + i * 8);
            cp_async16(stB + base + i * 16, Bg + off + i * 8);
        }
        cp_commit();
    }

    const uint32_t aBase = (uint32_t)((wm * 32 + (lane & 15)) * ROWB + (lane >> 4) * 16);
    const uint32_t bBase = (uint32_t)ATILE_B +
        (uint32_t)((wn * 64 + (lane & 7) + ((lane >> 4) << 3)) * ROWB +
                   ((lane >> 3) & 1) * 16);

    int stage = 0, nstage = 2;
    for (int it = 0; it < nk; ++it) {
        cp_wait<1>();
        __syncthreads();

        if (it + 2 < nk) {
            const uint32_t base = nstage * STAGE_B;
            const int off = (it + 2) * BK;
#pragma unroll
            for (int i = 0; i < 4; i++) {
                cp_async16(stA + base + i * 16, Ag + off + i * 8);
                cp_async16(stB + base + i * 16, Bg + off + i * 8);
            }
        }
        cp_commit();
        nstage = nstage + 1 == 3 ? 0 : nstage + 1;

        const uint32_t tb = sb + stage * STAGE_B;
        stage = stage + 1 == 3 ? 0 : stage + 1;

        uint32_t afr[2][2][4];
        ldsm4(afr[0][0][0], afr[0][0][1], afr[0][0][2], afr[0][0][3],
              tb + aBase);
        ldsm4(afr[0][1][0], afr[0][1][1], afr[0][1][2], afr[0][1][3],
              tb + aBase + 16 * ROWB);
#pragma unroll
        for (int ks = 0; ks < 4; ++ks) {
            const int cur = ks & 1, nxt = cur ^ 1;
            if (ks < 3) {
                ldsm4(afr[nxt][0][0], afr[nxt][0][1], afr[nxt][0][2], afr[nxt][0][3],
                      tb + aBase + (ks + 1) * 32);
                ldsm4(afr[nxt][1][0], afr[nxt][1][1], afr[nxt][1][2], afr[nxt][1][3],
                      tb + aBase + 16 * ROWB + (ks + 1) * 32);
            }
#pragma unroll
            for (int np = 0; np < 4; ++np) {
                uint32_t b0, b1, b2, b3;
                ldsm4(b0, b1, b2, b3, tb + bBase + np * 16 * ROWB + ks * 32);
                mma_f16(acc[0][2 * np],     afr[cur][0], b0, b1);
                mma_f16(acc[1][2 * np],     afr[cur][1], b0, b1);
                mma_f16(acc[0][2 * np + 1], afr[cur][0], b2, b3);
                mma_f16(acc[1][2 * np + 1], afr[cur][1], b2, b3);
            }
        }
    }

#pragma unroll
    for (int nt = 0; nt < 8; ++nt) {
        const int colb = bn + wn * 64 + nt * 8 + 2 * c;
        const float bz0 = bias[colb], bz1 = bias[colb + 1];
#pragma unroll
        for (int mt = 0; mt < 2; ++mt) {
            const int row0 = bm + wm * 32 + mt * 16 + g;
            float o0 = acc[mt][nt][0] + bz0;
            float o1 = acc[mt][nt][1] + bz1;
            float o2 = acc[mt][nt][2] + bz0;
            float o3 = acc[mt][nt][3] + bz1;
            if (ACT == 1) {
                o0 = fmaxf(o0, 0.f); o1 = fmaxf(o1, 0.f);
                o2 = fmaxf(o2, 0.f); o3 = fmaxf(o3, 0.f);
            }
            if (ACT == 2) {
                o0 = tanhf(o0); o1 = tanhf(o1);
                o2 = tanhf(o2); o3 = tanhf(o3);
            }
            if (sizeof(OutT) == 2) {
                *(__half2*)((__half*)C + (size_t)row0 * N + colb) =
                    __floats2half2_rn(o0, o1);
                *(__half2*)((__half*)C + (size_t)(row0 + 8) * N + colb) =
                    __floats2half2_rn(o2, o3);
            } else {
                *(float2*)((float*)C + (size_t)row0 * N + colb) = make_float2(o0, o1);
                *(float2*)((float*)C + (size_t)(row0 + 8) * N + colb) = make_float2(o2, o3);
            }
        }
    }
}

// ====== split-K fp16 GEMM: same tile, blockIdx.z = K-slice; fp32 partials ====
__global__ void __launch_bounds__(256, 2)
gemm_sk(const __half* __restrict__ A, const __half* __restrict__ W,
        float* __restrict__ P, int M, int N, int K, int kext)
{
    extern __shared__ char smc[];
    const uint32_t sb = smem_u32(smc);
    const int tid  = threadIdx.x;
    const int wid  = tid >> 5, lane = tid & 31;
    const int g    = lane >> 2, c = lane & 3;
    const int wm   = wid & 3, wn = wid >> 2;
    const int bm   = blockIdx.x * BM;
    const int bn   = blockIdx.y * BN;
    const int kst  = blockIdx.z * kext;
    float* Pz = P + (size_t)blockIdx.z * M * N;

    const int lrow = tid >> 1;
    const int lsel = tid & 1;
    const __half* Ag = A + (size_t)(bm + lrow) * K + kst + lsel * 32;
    const __half* Bg = W + (size_t)(bn + lrow) * K + kst + lsel * 32;
    const uint32_t stA = sb + (uint32_t)(lrow * ROWB + lsel * 64);
    const uint32_t stB = stA + ATILE_B;

    float acc[2][8][4];
#pragma unroll
    for (int mt = 0; mt < 2; mt++)
#pragma unroll
        for (int nt = 0; nt < 8; nt++)
#pragma unroll
            for (int r = 0; r < 4; r++) acc[mt][nt][r] = 0.0f;

    const int nk = kext / BK;

#pragma unroll
    for (int s = 0; s < 2; ++s) {
        const uint32_t base = s * STAGE_B;
        const int off = s * BK;
#pragma unroll
        for (int i = 0; i < 4; i++) {
            cp_async16(stA + base + i * 16, Ag + off + i * 8);
            cp_async16(stB + base + i * 16, Bg + off + i * 8);
        }
        cp_commit();
    }

    const uint32_t aBase = (uint32_t)((wm * 32 + (lane & 15)) * ROWB + (lane >> 4) * 16);
    const uint32_t bBase = (uint32_t)ATILE_B +
        (uint32_t)((wn * 64 + (lane & 7) + ((lane >> 4) << 3)) * ROWB +
                   ((lane >> 3) & 1) * 16);

    int stage = 0, nstage = 2;
    for (int it = 0; it < nk; ++it) {
        cp_wait<1>();
        __syncthreads();

        if (it + 2 < nk) {
            const uint32_t base = nstage * STAGE_B;
            const int off = (it + 2) * BK;
#pragma unroll
            for (int i = 0; i < 4; i++) {
                cp_async16(stA + base + i * 16, Ag + off + i * 8);
                cp_async16(stB + base + i * 16, Bg + off + i * 8);
            }
        }
        cp_commit();
        nstage = nstage + 1 == 3 ? 0 : nstage + 1;

        const uint32_t tb = sb + stage * STAGE_B;
        stage = stage + 1 == 3 ? 0 : stage + 1;

        uint32_t afr[2][2][4];
        ldsm4(afr[0][0][0], afr[0][0][1], afr[0][0][2], afr[0][0][3],
              tb + aBase);
        ldsm4(afr[0][1][0], afr[0][1][1], afr[0][1][2], afr[0][1][3],
              tb + aBase + 16 * ROWB);
#pragma unroll
        for (int ks = 0; ks < 4; ++ks) {
            const int cur = ks & 1, nxt = cur ^ 1;
            if (ks < 3) {
                ldsm4(afr[nxt][0][0], afr[nxt][0][1], afr[nxt][0][2], afr[nxt][0][3],
                      tb + aBase + (ks + 1) * 32);
                ldsm4(afr[nxt][1][0], afr[nxt][1][1], afr[nxt][1][2], afr[nxt][1][3],
                      tb + aBase + 16 * ROWB + (ks + 1) * 32);
            }
#pragma unroll
            for (int np = 0; np < 4; ++np) {
                uint32_t b0, b1, b2, b3;
                ldsm4(b0, b1, b2, b3, tb + bBase + np * 16 * ROWB + ks * 32);
                mma_f16(acc[0][2 * np],     afr[cur][0], b0, b1);
                mma_f16(acc[1][2 * np],     afr[cur][1], b0, b1);
                mma_f16(acc[0][2 * np + 1], afr[cur][0], b2, b3);
                mma_f16(acc[1][2 * np + 1], afr[cur][1], b2, b3);
            }
        }
    }

#pragma unroll
    for (int nt = 0; nt < 8; ++nt) {
        const int colb = bn + wn * 64 + nt * 8 + 2 * c;
#pragma unroll
        for (int mt = 0; mt < 2; ++mt) {
            const int row0 = bm + wm * 32 + mt * 16 + g;
            *(float2*)(Pz + (size_t)row0 * N + colb) =
                make_float2(acc[mt][nt][0], acc[mt][nt][1]);
            *(float2*)(Pz + (size_t)(row0 + 8) * N + colb) =
                make_float2(acc[mt][nt][2], acc[mt][nt][3]);
        }
    }
}

// ---- fused: split-K reduce + bias + power-norm + channel + LS + ZF ----------
// v2: warp handles TWO rows (doubles MLP; grid fits in one occupancy wave)
__global__ void __launch_bounds__(256)
channel_sk(const float* __restrict__ P, const float* __restrict__ bias,
           const float* __restrict__ noise, const float* __restrict__ h,
           __half* __restrict__ xr)
{
    const int lane = threadIdx.x & 31;
    const int row0 = blockIdx.x * 16 + (threadIdx.x >> 5) * 2;
    const float2* bp = (const float2*)bias;
    const float h0 = h[0], h1 = h[1];

    float2 sv[2][4], nv[2][4];
    float ss[2] = {0.f, 0.f};
#pragma unroll
    for (int r = 0; r < 2; ++r) {
        const int row = row0 + r;
        const float2* p0 = (const float2*)(P + (size_t)row * CH);
        const float2* p1 = (const float2*)(P + (size_t)BB * CH + (size_t)row * CH);
        const float2* np = (const float2*)(noise + (size_t)row * CH);
#pragma unroll
        for (int j = 0; j < 4; ++j) {
            const int idx = lane + 32 * j;
            float2 a = p0[idx], b = p1[idx], bz = bp[idx];
            sv[r][j].x = a.x + b.x + bz.x;
            sv[r][j].y = a.y + b.y + bz.y;
            nv[r][j] = np[idx];
            ss[r] += sv[r][j].x * sv[r][j].x + sv[r][j].y * sv[r][j].y;
        }
    }
#pragma unroll
    for (int o = 16; o; o >>= 1) {
        ss[0] += __shfl_xor_sync(0xffffffffu, ss[0], o);
        ss[1] += __shfl_xor_sync(0xffffffffu, ss[1], o);
    }

    float yr[2][4], yi[2][4];
    float numr[2] = {0.f, 0.f}, numi[2] = {0.f, 0.f};
#pragma unroll
    for (int r = 0; r < 2; ++r) {
        const float scale = sqrtf(128.0f) * rsqrtf(ss[r]);
#pragma unroll
        for (int j = 0; j < 4; ++j) {
            const float txr = scale * sv[r][j].x, txi = scale * sv[r][j].y;
            sv[r][j].x = txr; sv[r][j].y = txi;       // keep tx for LS below
            yr[r][j] = h0 * txr - h1 * txi + nv[r][j].x;
            yi[r][j] = h0 * txi + h1 * txr + nv[r][j].y;
            numr[r] += yr[r][j] * txr + yi[r][j] * txi;
            numi[r] += yi[r][j] * txr - yr[r][j] * txi;
        }
    }
#pragma unroll
    for (int o = 16; o; o >>= 1) {
        numr[0] += __shfl_xor_sync(0xffffffffu, numr[0], o);
        numi[0] += __shfl_xor_sync(0xffffffffu, numi[0], o);
        numr[1] += __shfl_xor_sync(0xffffffffu, numr[1], o);
        numi[1] += __shfl_xor_sync(0xffffffffu, numi[1], o);
    }
#pragma unroll
    for (int r = 0; r < 2; ++r) {
        const float hr = numr[r] * (1.0f / 128.0f);
        const float hi = numi[r] * (1.0f / 128.0f);
        const float inv = 1.0f / (hr * hr + hi * hi + 1e-12f);
        __half2* op = (__half2*)(xr + (size_t)(row0 + r) * CH);
#pragma unroll
        for (int j = 0; j < 4; ++j) {
            const float xe_r = (yr[r][j] * hr + yi[r][j] * hi) * inv;
            const float xe_i = (yi[r][j] * hr - yr[r][j] * hi) * inv;
            op[lane + 32 * j] = __floats2half2_rn(xe_r, xe_i);
        }
    }
}

// ---- RTN tail v2: 32 rows/block, smem-staged w_rtn3 --------------------------
__global__ void __launch_bounds__(256)
rtn_tail2(const __half* __restrict__ g2, const float* __restrict__ w_rtn3,
          const float* __restrict__ b_rtn3, const __half* __restrict__ xr,
          __half* __restrict__ xr2)
{
    __shared__ float ws[6][HR];     // 24 KB
    __shared__ float hs[32][6];

    const int tid  = threadIdx.x;
    const int warp = tid >> 5, lane = tid & 31;
    const int rb   = blockIdx.x * 32;

    for (int i = tid; i < 6 * HR; i += 256)
        ((float*)ws)[i] = w_rtn3[i];
    __syncthreads();

#pragma unroll
    for (int r = 0; r < 4; ++r) {
        const int row = rb + r * 8 + warp;
        const __half2* gp = (const __half2*)(g2 + (size_t)row * HR);
        float acc[6] = {0, 0, 0, 0, 0, 0};
#pragma unroll
        for (int j = 0; j < 16; ++j) {
            const float2 gv = __half22float2(gp[lane + 32 * j]);
            const int i0 = 2 * (lane + 32 * j);
#pragma unroll
            for (int o = 0; o < 6; ++o)
                acc[o] += gv.x * ws[o][i0] + gv.y * ws[o][i0 + 1];
        }
#pragma unroll
        for (int o = 0; o < 6; ++o) {
#pragma unroll
            for (int sft = 16; sft; sft >>= 1)
                acc[o] += __shfl_xor_sync(0xffffffffu, acc[o], sft);
        }
        if (lane < 6) hs[r * 8 + warp][lane] = acc[lane] + b_rtn3[lane];
    }
    __syncthreads();

    for (int idx = tid; idx < 32 * 128; idx += 256) {
        const int r = idx >> 7, t = idx & 127;
        const int row = rb + r;
        const __half2* xp = (const __half2*)(xr + (size_t)row * CH);
        float or_ = 0.0f, oi_ = 0.0f;
#pragma unroll
        for (int l = 0; l < 3; ++l) {
            if (t - l >= 0) {
                const float hrr = hs[r][2 * l], hii = hs[r][2 * l + 1];
                const float2 xv = __half22float2(xp[t - l]);
                or_ += hrr * xv.x - hii * xv.y;
                oi_ += hrr * xv.y + hii * xv.x;
            }
        }
        *(__half2*)(xr2 + (size_t)row * CH + 2 * t) = __floats2half2_rn(or_, oi_);
    }
}

// ---------------- launcher --------------------------------------------------
extern "C" void kernel_launch(void* const* d_in, const int* in_sizes, int n_in,
                              void* d_out, int out_size)
{
    const float* x     = (const float*)d_in[0];
    const float* w1    = (const float*)d_in[1];
    const float* b1    = (const float*)d_in[2];
    const float* w2    = (const float*)d_in[3];
    const float* b2    = (const float*)d_in[4];
    const float* wr1   = (const float*)d_in[5];
    const float* br1   = (const float*)d_in[6];
    const float* wr2   = (const float*)d_in[7];
    const float* br2   = (const float*)d_in[8];
    const float* wr3   = (const float*)d_in[9];
    const float* br3   = (const float*)d_in[10];
    const float* w3    = (const float*)d_in[11];
    const float* b3    = (const float*)d_in[12];
    const float* w4    = (const float*)d_in[13];
    const float* b4    = (const float*)d_in[14];
    const float* h     = (const float*)d_in[15];
    const float* noise = (const float*)d_in[16];

    __half *xh, *wh, *ah, *xrh, *g1h, *g2h, *x2h, *th;
    float  *p2;
    cudaGetSymbolAddress((void**)&xh,  g_xh);
    cudaGetSymbolAddress((void**)&wh,  g_wh);
    cudaGetSymbolAddress((void**)&ah,  g_ah);
    cudaGetSymbolAddress((void**)&xrh, g_xrh);
    cudaGetSymbolAddress((void**)&g1h, g_g1h);
    cudaGetSymbolAddress((void**)&g2h, g_g2h);
    cudaGetSymbolAddress((void**)&x2h, g_x2h);
    cudaGetSymbolAddress((void**)&th,  g_th);
    cudaGetSymbolAddress((void**)&p2,  g_p2);

    cudaFuncSetAttribute(gemm_h<1, __half>, cudaFuncAttributeMaxDynamicSharedMemorySize, SMEM3);
    cudaFuncSetAttribute(gemm_h<2, __half>, cudaFuncAttributeMaxDynamicSharedMemorySize, SMEM3);
    cudaFuncSetAttribute(gemm_h<0, float>,  cudaFuncAttributeMaxDynamicSharedMemorySize, SMEM3);
    cudaFuncSetAttribute(gemm_sk,           cudaFuncAttributeMaxDynamicSharedMemorySize, SMEM3);

    // single fused fp32 -> fp16 conversion (1 launch)
    ConvArgs ca;
    ca.src[0] = x;   ca.dst[0] = xh;            ca.n4[0] = BB * D_IN / 4;
    ca.src[1] = w1;  ca.dst[1] = wh + OFF_W1;   ca.n4[1] = H1 * D_IN / 4;
    ca.src[2] = w2;  ca.dst[2] = wh + OFF_W2;   ca.n4[2] = CH * H1 / 4;
    ca.src[3] = wr1; ca.dst[3] = wh + OFF_WR1;  ca.n4[3] = HR * CH / 4;
    ca.src[4] = wr2; ca.dst[4] = wh + OFF_WR2;  ca.n4[4] = HR * HR / 4;
    ca.src[5] = w3;  ca.dst[5] = wh + OFF_W3;   ca.n4[5] = H2 * CH / 4;
    ca.src[6] = w4;  ca.dst[6] = wh + OFF_W4;   ca.n4[6] = D_OUTN * H2 / 4;
    ca.src[7] = x;   ca.dst[7] = xh;            ca.n4[7] = 0;
    conv_all_kernel<<<1184, 256>>>(ca);

    // encoder
    gemm_h<1, __half><<<dim3(BB / BM, H1 / BN), 256, SMEM3>>>(
        xh, wh + OFF_W1, b1, ah, BB, H1, D_IN);
    // G2 via split-K (2 slices of K=2048); reduce fused into channel
    gemm_sk<<<dim3(BB / BM, CH / BN, 2), 256, SMEM3>>>(
        ah, wh + OFF_W2, p2, BB, CH, H1, H1 / 2);
    // fused reduce + bias + channel + equalization (2 rows per warp)
    channel_sk<<<BB / 16, 256>>>(p2, b2, noise, h, xrh);
    // RTN
    gemm_h<2, __half><<<dim3(BB / BM, HR / BN), 256, SMEM3>>>(
        xrh, wh + OFF_WR1, br1, g1h, BB, HR, CH);
    gemm_h<2, __half><<<dim3(BB / BM, HR / BN), 256, SMEM3>>>(
        g1h, wh + OFF_WR2, br2, g2h, BB, HR, HR);
    rtn_tail2<<<BB / 32, 256>>>(g2h, wr3, br3, xrh, x2h);
    // decoder
    gemm_h<1, __half><<<dim3(BB / BM, H2 / BN), 256, SMEM3>>>(
        x2h, wh + OFF_W3, b3, th, BB, H2, CH);
    gemm_h<0, float><<<dim3(BB / BM, D_OUTN / BN), 256, SMEM3>>>(
        th, wh + OFF_W4, b4, (float*)d_out, BB, D_OUTN, H2);
}

// round 16
// speedup vs baseline: 1.0253x; 1.0253x over previous
#include <cuda_runtime.h>
#include <cuda_fp16.h>
#include <cstdint>
#include <math.h>

#define BB    8192
#define D_IN  512
#define H1    4096
#define CH    256
#define HR    1024
#define H2    4096
#define D_OUTN 512

// ---------------- scratch (device globals; no allocation allowed) ----------
__device__ __half g_xh [(size_t)BB * D_IN];
__device__ __half g_wh [(size_t)7602176];       // all weights, fp16
__device__ __half g_ah [(size_t)BB * H1];
__device__ __half g_xrh[(size_t)BB * CH];
__device__ __half g_g1h[(size_t)BB * HR];
__device__ __half g_g2h[(size_t)BB * HR];
__device__ __half g_x2h[(size_t)BB * CH];
__device__ __half g_th [(size_t)BB * H2];
__device__ float  g_p2 [(size_t)2 * BB * CH];   // split-K partials for G2

#define OFF_W1  0
#define OFF_W2  2097152
#define OFF_WR1 3145728
#define OFF_WR2 3407872
#define OFF_W3  4456448
#define OFF_W4  5505024

// ---------------- helpers ----------------------------------------------------
__device__ __forceinline__ uint32_t smem_u32(const void* p) {
    uint32_t a;
    asm("{ .reg .u64 t; cvta.to.shared.u64 t, %1; cvt.u32.u64 %0, t; }"
        : "=r"(a) : "l"(p));
    return a;
}

__device__ __forceinline__ void cp_async16(uint32_t dst, const void* src) {
    asm volatile("cp.async.cg.shared.global [%0], [%1], 16;"
        :: "r"(dst), "l"(src) : "memory");
}
__device__ __forceinline__ void cp_commit() {
    asm volatile("cp.async.commit_group;" ::: "memory");
}
template <int N>
__device__ __forceinline__ void cp_wait() {
    asm volatile("cp.async.wait_group %0;" :: "n"(N) : "memory");
}

__device__ __forceinline__ void pdl_wait() {
    asm volatile("griddepcontrol.wait;" ::: "memory");
}
__device__ __forceinline__ void pdl_trigger() {
    asm volatile("griddepcontrol.launch_dependents;" ::: "memory");
}

__device__ __forceinline__ void ldsm4(uint32_t& r0, uint32_t& r1,
                                      uint32_t& r2, uint32_t& r3, uint32_t a) {
    asm volatile("ldmatrix.sync.aligned.m8n8.x4.shared.b16 {%0,%1,%2,%3}, [%4];"
        : "=r"(r0), "=r"(r1), "=r"(r2), "=r"(r3) : "r"(a));
}

__device__ __forceinline__ void mma_f16(float* d, const uint32_t* a,
                                        uint32_t b0, uint32_t b1) {
    asm volatile(
        "mma.sync.aligned.m16n8k16.row.col.f32.f16.f16.f32 "
        "{%0,%1,%2,%3}, {%4,%5,%6,%7}, {%8,%9}, {%0,%1,%2,%3};"
        : "+f"(d[0]), "+f"(d[1]), "+f"(d[2]), "+f"(d[3])
        : "r"(a[0]), "r"(a[1]), "r"(a[2]), "r"(a[3]), "r"(b0), "r"(b1));
}

// ---------------- single fused fp32 -> fp16 conversion pass ------------------
struct ConvArgs {
    const float* src[8];
    __half*      dst[8];
    int          n4[8];
};

__global__ void conv_all_kernel(ConvArgs a) {
    const int stride = gridDim.x * blockDim.x;
    const int t0 = blockIdx.x * blockDim.x + threadIdx.x;
#pragma unroll
    for (int s = 0; s < 8; ++s) {
        const float4* sp = (const float4*)a.src[s];
        __half2* dp = (__half2*)a.dst[s];
        const int n = a.n4[s];
        for (int i = t0; i < n; i += stride) {
            float4 v = sp[i];
            dp[2 * i]     = __floats2half2_rn(v.x, v.y);
            dp[2 * i + 1] = __floats2half2_rn(v.z, v.w);
        }
    }
}

// =============== fp16 GEMM: 128x128x64, 3-stage, 2 CTAs/SM ===================
// PDL=1: B (weight) stages prefetched BEFORE griddepcontrol.wait; A after.
#define BM 128
#define BN 128
#define BK 64
#define ROWB 144                      // padded row bytes (72 halfs)
#define ATILE_B (128 * ROWB)          // 18432
#define STAGE_B (2 * ATILE_B)         // 36864 (A + B)
#define SMEM3   (3 * STAGE_B)         // 110592

template <int ACT, typename OutT, int PDL>  // ACT: 0 none, 1 relu, 2 tanh
__global__ void __launch_bounds__(256, 2)
gemm_h(const __half* __restrict__ A, const __half* __restrict__ W,
       const float* __restrict__ bias, OutT* __restrict__ C,
       int M, int N, int K)
{
    extern __shared__ char smc[];
    const uint32_t sb = smem_u32(smc);
    const int tid  = threadIdx.x;
    const int wid  = tid >> 5, lane = tid & 31;
    const int g    = lane >> 2, c = lane & 3;
    const int wm   = wid & 3, wn = wid >> 2;      // warp grid 4(M) x 2(N)
    const int bm   = blockIdx.x * BM;
    const int bn   = blockIdx.y * BN;

    const int lrow = tid >> 1;
    const int lsel = tid & 1;
    const __half* Ag = A + (size_t)(bm + lrow) * K + lsel * 32;
    const __half* Bg = W + (size_t)(bn + lrow) * K + lsel * 32;
    const uint32_t stA = sb + (uint32_t)(lrow * ROWB + lsel * 64);
    const uint32_t stB = stA + ATILE_B;

    float acc[2][8][4];
#pragma unroll
    for (int mt = 0; mt < 2; mt++)
#pragma unroll
        for (int nt = 0; nt < 8; nt++)
#pragma unroll
            for (int r = 0; r < 4; r++) acc[mt][nt][r] = 0.0f;

    const int nk = K / BK;

    if (PDL) {
        // weights are ready before the chain: prefetch B for stages 0,1 now
#pragma unroll
        for (int s = 0; s < 2; ++s) {
            const uint32_t base = s * STAGE_B;
            const int off = s * BK;
#pragma unroll
            for (int i = 0; i < 4; i++)
                cp_async16(stB + base + i * 16, Bg + off + i * 8);
        }
        pdl_wait();   // A (predecessor output) must be visible from here on
#pragma unroll
        for (int s = 0; s < 2; ++s) {
            const uint32_t base = s * STAGE_B;
            const int off = s * BK;
#pragma unroll
            for (int i = 0; i < 4; i++)
                cp_async16(stA + base + i * 16, Ag + off + i * 8);
            cp_commit();   // group0={B0,B1,A0}, group1={A1}
        }
    } else {
#pragma unroll
        for (int s = 0; s < 2; ++s) {
            const uint32_t base = s * STAGE_B;
            const int off = s * BK;
#pragma unroll
            for (int i = 0; i < 4; i++) {
                cp_async16(stA + base + i * 16, Ag + off + i * 8);
                cp_async16(stB + base + i * 16, Bg + off + i * 8);
            }
            cp_commit();
        }
    }

    const uint32_t aBase = (uint32_t)((wm * 32 + (lane & 15)) * ROWB + (lane >> 4) * 16);
    const uint32_t bBase = (uint32_t)ATILE_B +
        (uint32_t)((wn * 64 + (lane & 7) + ((lane >> 4) << 3)) * ROWB +
                   ((lane >> 3) & 1) * 16);

    int stage = 0, nstage = 2;
    for (int it = 0; it < nk; ++it) {
        cp_wait<1>();
        __syncthreads();

        if (it + 2 < nk) {
            const uint32_t base = nstage * STAGE_B;
            const int off = (it + 2) * BK;
#pragma unroll
            for (int i = 0; i < 4; i++) {
                cp_async16(stA + base + i * 16, Ag + off + i * 8);
                cp_async16(stB + base + i * 16, Bg + off + i * 8);
            }
        }
        cp_commit();
        nstage = nstage + 1 == 3 ? 0 : nstage + 1;

        const uint32_t tb = sb + stage * STAGE_B;
        stage = stage + 1 == 3 ? 0 : stage + 1;

        uint32_t afr[2][2][4];
        ldsm4(afr[0][0][0], afr[0][0][1], afr[0][0][2], afr[0][0][3],
              tb + aBase);
        ldsm4(afr[0][1][0], afr[0][1][1], afr[0][1][2], afr[0][1][3],
              tb + aBase + 16 * ROWB);
#pragma unroll
        for (int ks = 0; ks < 4; ++ks) {
            const int cur = ks & 1, nxt = cur ^ 1;
            if (ks < 3) {
                ldsm4(afr[nxt][0][0], afr[nxt][0][1], afr[nxt][0][2], afr[nxt][0][3],
                      tb + aBase + (ks + 1) * 32);
                ldsm4(afr[nxt][1][0], afr[nxt][1][1], afr[nxt][1][2], afr[nxt][1][3],
                      tb + aBase + 16 * ROWB + (ks + 1) * 32);
            }
#pragma unroll
            for (int np = 0; np < 4; ++np) {
                uint32_t b0, b1, b2, b3;
                ldsm4(b0, b1, b2, b3, tb + bBase + np * 16 * ROWB + ks * 32);
                mma_f16(acc[0][2 * np],     afr[cur][0], b0, b1);
                mma_f16(acc[1][2 * np],     afr[cur][1], b0, b1);
                mma_f16(acc[0][2 * np + 1], afr[cur][0], b2, b3);
                mma_f16(acc[1][2 * np + 1], afr[cur][1], b2, b3);
            }
        }
    }

    pdl_trigger();   // mainloop done: allow dependent kernel to launch

#pragma unroll
    for (int nt = 0; nt < 8; ++nt) {
        const int colb = bn + wn * 64 + nt * 8 + 2 * c;
        const float bz0 = bias[colb], bz1 = bias[colb + 1];
#pragma unroll
        for (int mt = 0; mt < 2; ++mt) {
            const int row0 = bm + wm * 32 + mt * 16 + g;
            float o0 = acc[mt][nt][0] + bz0;
            float o1 = acc[mt][nt][1] + bz1;
            float o2 = acc[mt][nt][2] + bz0;
            float o3 = acc[mt][nt][3] + bz1;
            if (ACT == 1) {
                o0 = fmaxf(o0, 0.f); o1 = fmaxf(o1, 0.f);
                o2 = fmaxf(o2, 0.f); o3 = fmaxf(o3, 0.f);
            }
            if (ACT == 2) {
                o0 = tanhf(o0); o1 = tanhf(o1);
                o2 = tanhf(o2); o3 = tanhf(o3);
            }
            if (sizeof(OutT) == 2) {
                *(__half2*)((__half*)C + (size_t)row0 * N + colb) =
                    __floats2half2_rn(o0, o1);
                *(__half2*)((__half*)C + (size_t)(row0 + 8) * N + colb) =
                    __floats2half2_rn(o2, o3);
            } else {
                *(float2*)((float*)C + (size_t)row0 * N + colb) = make_float2(o0, o1);
                *(float2*)((float*)C + (size_t)(row0 + 8) * N + colb) = make_float2(o2, o3);
            }
        }
    }
}

// ====== split-K fp16 GEMM (PDL): blockIdx.z = K-slice; fp32 partials =========
__global__ void __launch_bounds__(256, 2)
gemm_sk(const __half* __restrict__ A, const __half* __restrict__ W,
        float* __restrict__ P, int M, int N, int K, int kext)
{
    extern __shared__ char smc[];
    const uint32_t sb = smem_u32(smc);
    const int tid  = threadIdx.x;
    const int wid  = tid >> 5, lane = tid & 31;
    const int g    = lane >> 2, c = lane & 3;
    const int wm   = wid & 3, wn = wid >> 2;
    const int bm   = blockIdx.x * BM;
    const int bn   = blockIdx.y * BN;
    const int kst  = blockIdx.z * kext;
    float* Pz = P + (size_t)blockIdx.z * M * N;

    const int lrow = tid >> 1;
    const int lsel = tid & 1;
    const __half* Ag = A + (size_t)(bm + lrow) * K + kst + lsel * 32;
    const __half* Bg = W + (size_t)(bn + lrow) * K + kst + lsel * 32;
    const uint32_t stA = sb + (uint32_t)(lrow * ROWB + lsel * 64);
    const uint32_t stB = stA + ATILE_B;

    float acc[2][8][4];
#pragma unroll
    for (int mt = 0; mt < 2; mt++)
#pragma unroll
        for (int nt = 0; nt < 8; nt++)
#pragma unroll
            for (int r = 0; r < 4; r++) acc[mt][nt][r] = 0.0f;

    const int nk = kext / BK;

    // PDL prologue: B first, wait, then A
#pragma unroll
    for (int s = 0; s < 2; ++s) {
        const uint32_t base = s * STAGE_B;
        const int off = s * BK;
#pragma unroll
        for (int i = 0; i < 4; i++)
            cp_async16(stB + base + i * 16, Bg + off + i * 8);
    }
    pdl_wait();
#pragma unroll
    for (int s = 0; s < 2; ++s) {
        const uint32_t base = s * STAGE_B;
        const int off = s * BK;
#pragma unroll
        for (int i = 0; i < 4; i++)
            cp_async16(stA + base + i * 16, Ag + off + i * 8);
        cp_commit();
    }

    const uint32_t aBase = (uint32_t)((wm * 32 + (lane & 15)) * ROWB + (lane >> 4) * 16);
    const uint32_t bBase = (uint32_t)ATILE_B +
        (uint32_t)((wn * 64 + (lane & 7) + ((lane >> 4) << 3)) * ROWB +
                   ((lane >> 3) & 1) * 16);

    int stage = 0, nstage = 2;
    for (int it = 0; it < nk; ++it) {
        cp_wait<1>();
        __syncthreads();

        if (it + 2 < nk) {
            const uint32_t base = nstage * STAGE_B;
            const int off = (it + 2) * BK;
#pragma unroll
            for (int i = 0; i < 4; i++) {
                cp_async16(stA + base + i * 16, Ag + off + i * 8);
                cp_async16(stB + base + i * 16, Bg + off + i * 8);
            }
        }
        cp_commit();
        nstage = nstage + 1 == 3 ? 0 : nstage + 1;

        const uint32_t tb = sb + stage * STAGE_B;
        stage = stage + 1 == 3 ? 0 : stage + 1;

        uint32_t afr[2][2][4];
        ldsm4(afr[0][0][0], afr[0][0][1], afr[0][0][2], afr[0][0][3],
              tb + aBase);
        ldsm4(afr[0][1][0], afr[0][1][1], afr[0][1][2], afr[0][1][3],
              tb + aBase + 16 * ROWB);
#pragma unroll
        for (int ks = 0; ks < 4; ++ks) {
            const int cur = ks & 1, nxt = cur ^ 1;
            if (ks < 3) {
                ldsm4(afr[nxt][0][0], afr[nxt][0][1], afr[nxt][0][2], afr[nxt][0][3],
                      tb + aBase + (ks + 1) * 32);
                ldsm4(afr[nxt][1][0], afr[nxt][1][1], afr[nxt][1][2], afr[nxt][1][3],
                      tb + aBase + 16 * ROWB + (ks + 1) * 32);
            }
#pragma unroll
            for (int np = 0; np < 4; ++np) {
                uint32_t b0, b1, b2, b3;
                ldsm4(b0, b1, b2, b3, tb + bBase + np * 16 * ROWB + ks * 32);
                mma_f16(acc[0][2 * np],     afr[cur][0], b0, b1);
                mma_f16(acc[1][2 * np],     afr[cur][1], b0, b1);
                mma_f16(acc[0][2 * np + 1], afr[cur][0], b2, b3);
                mma_f16(acc[1][2 * np + 1], afr[cur][1], b2, b3);
            }
        }
    }

    pdl_trigger();

#pragma unroll
    for (int nt = 0; nt < 8; ++nt) {
        const int colb = bn + wn * 64 + nt * 8 + 2 * c;
#pragma unroll
        for (int mt = 0; mt < 2; ++mt) {
            const int row0 = bm + wm * 32 + mt * 16 + g;
            *(float2*)(Pz + (size_t)row0 * N + colb) =
                make_float2(acc[mt][nt][0], acc[mt][nt][1]);
            *(float2*)(Pz + (size_t)(row0 + 8) * N + colb) =
                make_float2(acc[mt][nt][2], acc[mt][nt][3]);
        }
    }
}

// ---- fused: split-K reduce + bias + power-norm + channel + LS + ZF (R14) ----
__global__ void __launch_bounds__(256)
channel_sk(const float* __restrict__ P, const float* __restrict__ bias,
           const float* __restrict__ noise, const float* __restrict__ h,
           __half* __restrict__ xr)
{
    pdl_trigger();   // let next GEMM prefetch its weight tiles immediately
    pdl_wait();      // our inputs come from gemm_sk

    const int lane = threadIdx.x & 31;
    const int row  = blockIdx.x * 8 + (threadIdx.x >> 5);
    const float2* p0 = (const float2*)(P + (size_t)row * CH);
    const float2* p1 = (const float2*)(P + (size_t)BB * CH + (size_t)row * CH);
    const float2* np = (const float2*)(noise + (size_t)row * CH);
    const float2* bp = (const float2*)bias;

    float2 sv[4], nv[4];
    float sumsq = 0.f;
#pragma unroll
    for (int j = 0; j < 4; ++j) {
        const int idx = lane + 32 * j;
        float2 a = p0[idx], b = p1[idx], bz = bp[idx & 127];
        sv[j].x = a.x + b.x + bz.x;
        sv[j].y = a.y + b.y + bz.y;
        nv[j] = np[idx];
        sumsq += sv[j].x * sv[j].x + sv[j].y * sv[j].y;
    }
#pragma unroll
    for (int o = 16; o; o >>= 1) sumsq += __shfl_xor_sync(0xffffffffu, sumsq, o);
    const float scale = sqrtf(128.0f) * rsqrtf(sumsq);
    const float h0 = h[0], h1 = h[1];

    float yr[4], yi[4];
    float numr = 0.f, numi = 0.f;
#pragma unroll
    for (int j = 0; j < 4; ++j) {
        const float txr = scale * sv[j].x, txi = scale * sv[j].y;
        yr[j] = h0 * txr - h1 * txi + nv[j].x;
        yi[j] = h0 * txi + h1 * txr + nv[j].y;
        numr += yr[j] * txr + yi[j] * txi;
        numi += yi[j] * txr - yr[j] * txi;
    }
#pragma unroll
    for (int o = 16; o; o >>= 1) {
        numr += __shfl_xor_sync(0xffffffffu, numr, o);
        numi += __shfl_xor_sync(0xffffffffu, numi, o);
    }
    const float hr = numr * (1.0f / 128.0f);
    const float hi = numi * (1.0f / 128.0f);
    const float inv = 1.0f / (hr * hr + hi * hi + 1e-12f);
    __half2* op = (__half2*)(xr + (size_t)row * CH);
#pragma unroll
    for (int j = 0; j < 4; ++j) {
        const float xe_r = (yr[j] * hr + yi[j] * hi) * inv;
        const float xe_i = (yi[j] * hr - yr[j] * hi) * inv;
        op[lane + 32 * j] = __floats2half2_rn(xe_r, xe_i);
    }
}

// ---- RTN tail v2: 32 rows/block, smem-staged w_rtn3 --------------------------
__global__ void __launch_bounds__(256)
rtn_tail2(const __half* __restrict__ g2, const float* __restrict__ w_rtn3,
          const float* __restrict__ b_rtn3, const __half* __restrict__ xr,
          __half* __restrict__ xr2)
{
    __shared__ float ws[6][HR];     // 24 KB
    __shared__ float hs[32][6];

    pdl_trigger();   // let next GEMM prefetch its weight tiles immediately

    const int tid  = threadIdx.x;
    const int warp = tid >> 5, lane = tid & 31;
    const int rb   = blockIdx.x * 32;

    // stage w_rtn3 (weights: ready pre-chain)
    for (int i = tid; i < 6 * HR; i += 256)
        ((float*)ws)[i] = w_rtn3[i];
    pdl_wait();      // g2 comes from the preceding GEMM
    __syncthreads();

#pragma unroll
    for (int r = 0; r < 4; ++r) {
        const int row = rb + r * 8 + warp;
        const __half2* gp = (const __half2*)(g2 + (size_t)row * HR);
        float acc[6] = {0, 0, 0, 0, 0, 0};
#pragma unroll
        for (int j = 0; j < 16; ++j) {
            const float2 gv = __half22float2(gp[lane + 32 * j]);
            const int i0 = 2 * (lane + 32 * j);
#pragma unroll
            for (int o = 0; o < 6; ++o)
                acc[o] += gv.x * ws[o][i0] + gv.y * ws[o][i0 + 1];
        }
#pragma unroll
        for (int o = 0; o < 6; ++o) {
#pragma unroll
            for (int sft = 16; sft; sft >>= 1)
                acc[o] += __shfl_xor_sync(0xffffffffu, acc[o], sft);
        }
        if (lane < 6) hs[r * 8 + warp][lane] = acc[lane] + b_rtn3[lane];
    }
    __syncthreads();

    for (int idx = tid; idx < 32 * 128; idx += 256) {
        const int r = idx >> 7, t = idx & 127;
        const int row = rb + r;
        const __half2* xp = (const __half2*)(xr + (size_t)row * CH);
        float or_ = 0.0f, oi_ = 0.0f;
#pragma unroll
        for (int l = 0; l < 3; ++l) {
            if (t - l >= 0) {
                const float hrr = hs[r][2 * l], hii = hs[r][2 * l + 1];
                const float2 xv = __half22float2(xp[t - l]);
                or_ += hrr * xv.x - hii * xv.y;
                oi_ += hrr * xv.y + hii * xv.x;
            }
        }
        *(__half2*)(xr2 + (size_t)row * CH + 2 * t) = __floats2half2_rn(or_, oi_);
    }
}

// ---------------- launcher --------------------------------------------------
static void launch_pdl(void* fn, dim3 grid, void** args, size_t smem)
{
    cudaLaunchConfig_t cfg = {};
    cfg.gridDim = grid;
    cfg.blockDim = dim3(256, 1, 1);
    cfg.dynamicSmemBytes = smem;
    cfg.stream = 0;
    cudaLaunchAttribute at[1];
    at[0].id = cudaLaunchAttributeProgrammaticStreamSerialization;
    at[0].val.programmaticStreamSerializationAllowed = 1;
    cfg.attrs = at;
    cfg.numAttrs = 1;
    cudaLaunchKernelExC(&cfg, fn, args);
}

extern "C" void kernel_launch(void* const* d_in, const int* in_sizes, int n_in,
                              void* d_out, int out_size)
{
    const float* x     = (const float*)d_in[0];
    const float* w1    = (const float*)d_in[1];
    const float* b1    = (const float*)d_in[2];
    const float* w2    = (const float*)d_in[3];
    const float* b2    = (const float*)d_in[4];
    const float* wr1   = (const float*)d_in[5];
    const float* br1   = (const float*)d_in[6];
    const float* wr2   = (const float*)d_in[7];
    const float* br2   = (const float*)d_in[8];
    const float* wr3   = (const float*)d_in[9];
    const float* br3   = (const float*)d_in[10];
    const float* w3    = (const float*)d_in[11];
    const float* b3    = (const float*)d_in[12];
    const float* w4    = (const float*)d_in[13];
    const float* b4    = (const float*)d_in[14];
    const float* h     = (const float*)d_in[15];
    const float* noise = (const float*)d_in[16];

    __half *xh, *wh, *ah, *xrh, *g1h, *g2h, *x2h, *th;
    float  *p2;
    cudaGetSymbolAddress((void**)&xh,  g_xh);
    cudaGetSymbolAddress((void**)&wh,  g_wh);
    cudaGetSymbolAddress((void**)&ah,  g_ah);
    cudaGetSymbolAddress((void**)&xrh, g_xrh);
    cudaGetSymbolAddress((void**)&g1h, g_g1h);
    cudaGetSymbolAddress((void**)&g2h, g_g2h);
    cudaGetSymbolAddress((void**)&x2h, g_x2h);
    cudaGetSymbolAddress((void**)&th,  g_th);
    cudaGetSymbolAddress((void**)&p2,  g_p2);

    cudaFuncSetAttribute(gemm_h<1, __half, 0>, cudaFuncAttributeMaxDynamicSharedMemorySize, SMEM3);
    cudaFuncSetAttribute(gemm_h<2, __half, 1>, cudaFuncAttributeMaxDynamicSharedMemorySize, SMEM3);
    cudaFuncSetAttribute(gemm_h<1, __half, 1>, cudaFuncAttributeMaxDynamicSharedMemorySize, SMEM3);
    cudaFuncSetAttribute(gemm_h<0, float, 1>,  cudaFuncAttributeMaxDynamicSharedMemorySize, SMEM3);
    cudaFuncSetAttribute(gemm_sk,              cudaFuncAttributeMaxDynamicSharedMemorySize, SMEM3);

    // single fused fp32 -> fp16 conversion (1 launch)
    ConvArgs ca;
    ca.src[0] = x;   ca.dst[0] = xh;            ca.n4[0] = BB * D_IN / 4;
    ca.src[1] = w1;  ca.dst[1] = wh + OFF_W1;   ca.n4[1] = H1 * D_IN / 4;
    ca.src[2] = w2;  ca.dst[2] = wh + OFF_W2;   ca.n4[2] = CH * H1 / 4;
    ca.src[3] = wr1; ca.dst[3] = wh + OFF_WR1;  ca.n4[3] = HR * CH / 4;
    ca.src[4] = wr2; ca.dst[4] = wh + OFF_WR2;  ca.n4[4] = HR * HR / 4;
    ca.src[5] = w3;  ca.dst[5] = wh + OFF_W3;   ca.n4[5] = H2 * CH / 4;
    ca.src[6] = w4;  ca.dst[6] = wh + OFF_W4;   ca.n4[6] = D_OUTN * H2 / 4;
    ca.src[7] = x;   ca.dst[7] = xh;            ca.n4[7] = 0;
    conv_all_kernel<<<1184, 256>>>(ca);

    // G1 (non-PDL: its weights come from the immediately preceding conv)
    gemm_h<1, __half, 0><<<dim3(BB / BM, H1 / BN), 256, SMEM3>>>(
        xh, wh + OFF_W1, b1, ah, BB, H1, D_IN);

    // G2 split-K (PDL after G1)
    {
        const __half* A = ah; const __half* W = wh + OFF_W2; float* P = p2;
        int M = BB, N = CH, K = H1, kext = H1 / 2;
        void* args[] = {&A, &W, &P, &M, &N, &K, &kext};
        launch_pdl((void*)gemm_sk, dim3(BB / BM, CH / BN, 2), args, SMEM3);
    }
    // channel (plain launch; triggers early for G3)
    channel_sk<<<BB / 8, 256>>>(p2, b2, noise, h, xrh);
    // G3 (PDL after channel)
    {
        const __half* A = xrh; const __half* W = wh + OFF_WR1;
        const float* bs = br1; __half* C = g1h;
        int M = BB, N = HR, K = CH;
        void* args[] = {&A, &W, &bs, &C, &M, &N, &K};
        launch_pdl((void*)gemm_h<2, __half, 1>, dim3(BB / BM, HR / BN), args, SMEM3);
    }
    // G4 (PDL after G3)
    {
        const __half* A = g1h; const __half* W = wh + OFF_WR2;
        const float* bs = br2; __half* C = g2h;
        int M = BB, N = HR, K = HR;
        void* args[] = {&A, &W, &bs, &C, &M, &N, &K};
        launch_pdl((void*)gemm_h<2, __half, 1>, dim3(BB / BM, HR / BN), args, SMEM3);
    }
    // rtn tail (plain launch; triggers early for G5)
    rtn_tail2<<<BB / 32, 256>>>(g2h, wr3, br3, xrh, x2h);
    // G5 (PDL after rtn_tail2)
    {
        const __half* A = x2h; const __half* W = wh + OFF_W3;
        const float* bs = b3; __half* C = th;
        int M = BB, N = H2, K = CH;
        void* args[] = {&A, &W, &bs, &C, &M, &N, &K};
        launch_pdl((void*)gemm_h<1, __half, 1>, dim3(BB / BM, H2 / BN), args, SMEM3);
    }
    // G6 (PDL after G5)
    {
        const __half* A = th; const __half* W = wh + OFF_W4;
        const float* bs = b4; float* C = (float*)d_out;
        int M = BB, N = D_OUTN, K = H2;
        void* args[] = {&A, &W, &bs, &C, &M, &N, &K};
        launch_pdl((void*)gemm_h<0, float, 1>, dim3(BB / BM, D_OUTN / BN), args, SMEM3);
    }
}